// round 1
// baseline (speedup 1.0000x reference)
#include <cuda_runtime.h>

#define FFEAT   32
#define DDIM    64
#define P_PAIRS 496
#define BT      256
#define THREADS 256
#define XPAD    65   // pad row to 65 floats: conflict-free sX[row][k] column reads

#define SW_FLOATS (DDIM * DDIM)        // 4096
#define SX_FLOATS (BT * XPAD)          // 16640
#define SMEM_BYTES ((SW_FLOATS + SX_FLOATS) * 4)   // 82944 bytes

__device__ __forceinline__ unsigned long long pack2(float x) {
    unsigned long long r;
    asm("mov.b64 %0, {%1, %1};" : "=l"(r) : "f"(x));
    return r;
}
__device__ __forceinline__ void fma2(unsigned long long& d, unsigned long long a, unsigned long long b) {
    asm("fma.rn.f32x2 %0, %1, %2, %0;" : "+l"(d) : "l"(a), "l"(b));
}
__device__ __forceinline__ float2 unpack2(unsigned long long a) {
    float2 f;
    asm("mov.b64 {%0, %1}, %2;" : "=f"(f.x), "=f"(f.y) : "l"(a));
    return f;
}

__global__ void __launch_bounds__(THREADS, 2)
bilinear_kernel(const float* __restrict__ X,   // [B, F, D]
                const float* __restrict__ W,   // [P, D, D]
                float* __restrict__ out)       // [B, P, D]
{
    extern __shared__ float smem[];
    float* sW = smem;              // [64][64]
    float* sX = smem + SW_FLOATS;  // [256][65]

    const int p   = blockIdx.y;
    const int b0  = blockIdx.x * BT;
    const int tid = threadIdx.x;

    // decode pair (i, j) from p (triu, k=1, row-major)
    int i = 0, rem = p;
    while (rem >= FFEAT - 1 - i) { rem -= FFEAT - 1 - i; i++; }
    const int j = i + 1 + rem;

    // ---- load W_p (4096 floats) : 16 floats/thread, coalesced float4 ----
    {
        const float4* wg = (const float4*)(W + (size_t)p * DDIM * DDIM);
        float4* ws = (float4*)sW;
        #pragma unroll
        for (int t = 0; t < 4; t++)
            ws[tid + t * THREADS] = wg[tid + t * THREADS];
    }
    // ---- load X_i tile: 256 rows x 64 floats ----
    {
        const int r  = tid >> 4;          // 0..15
        const int d4 = (tid & 15) * 4;    // 0,4,...,60
        #pragma unroll
        for (int t = 0; t < 16; t++) {
            const int row = r + t * 16;
            float4 v = *(const float4*)(X + ((size_t)(b0 + row) * FFEAT + i) * DDIM + d4);
            float* dst = sX + row * XPAD + d4;
            dst[0] = v.x; dst[1] = v.y; dst[2] = v.z; dst[3] = v.w;
        }
    }
    __syncthreads();

    const int rg = tid >> 3;   // 32 row-groups of 8 rows
    const int cg = tid & 7;    // 8 col-groups of 8 cols
    const int e0 = cg * 8;
    const int r0 = rg * 8;

    unsigned long long acc[8][4];
    #pragma unroll
    for (int r = 0; r < 8; r++)
        #pragma unroll
        for (int c = 0; c < 4; c++) acc[r][c] = 0ull;

    // main loop: acc[r][e-pair] += (x,x) * (W[k][e], W[k][e+1]) via fma.rn.f32x2
    #pragma unroll 4
    for (int k = 0; k < DDIM; k++) {
        const ulonglong2* wp = (const ulonglong2*)(sW + k * DDIM + e0);
        const ulonglong2 w01 = wp[0];
        const ulonglong2 w23 = wp[1];
        #pragma unroll
        for (int r = 0; r < 8; r++) {
            const unsigned long long xp = pack2(sX[(r0 + r) * XPAD + k]);
            fma2(acc[r][0], xp, w01.x);
            fma2(acc[r][1], xp, w01.y);
            fma2(acc[r][2], xp, w23.x);
            fma2(acc[r][3], xp, w23.y);
        }
    }

    // epilogue: out[b,p,e] = acc * X[b, j, e]  (X_j read through L2, fully resident)
    #pragma unroll
    for (int r = 0; r < 8; r++) {
        const int row = b0 + r0 + r;
        const float4* xj = (const float4*)(X + ((size_t)row * FFEAT + j) * DDIM + e0);
        const float4 j0 = xj[0];
        const float4 j1 = xj[1];
        const float2 a0 = unpack2(acc[r][0]);
        const float2 a1 = unpack2(acc[r][1]);
        const float2 a2 = unpack2(acc[r][2]);
        const float2 a3 = unpack2(acc[r][3]);
        float4 o0 = make_float4(a0.x * j0.x, a0.y * j0.y, a1.x * j0.z, a1.y * j0.w);
        float4 o1 = make_float4(a2.x * j1.x, a2.y * j1.y, a3.x * j1.z, a3.y * j1.w);
        float4* op = (float4*)(out + ((size_t)row * P_PAIRS + p) * DDIM + e0);
        op[0] = o0;
        op[1] = o1;
    }
}

extern "C" void kernel_launch(void* const* d_in, const int* in_sizes, int n_in,
                              void* d_out, int out_size) {
    const float* X = (const float*)d_in[0];   // inputs [4096, 32, 64]
    const float* W = (const float*)d_in[1];   // W      [496, 64, 64]
    float* out = (float*)d_out;               // [4096, 496, 64]

    const int B = in_sizes[0] / (FFEAT * DDIM);   // 4096

    cudaFuncSetAttribute(bilinear_kernel,
                         cudaFuncAttributeMaxDynamicSharedMemorySize, SMEM_BYTES);

    dim3 grid(B / BT, P_PAIRS);
    bilinear_kernel<<<grid, THREADS, SMEM_BYTES>>>(X, W, out);
}

// round 3
// speedup vs baseline: 1.8713x; 1.8713x over previous
#include <cuda_runtime.h>
#include <cuda_bf16.h>
#include <stdint.h>

#define FFEAT   32
#define DDIM    64
#define P_PAIRS 496
#define FD      (FFEAT * DDIM)   // 2048
#define MT      128
#define THREADS 128

// smem: A_hi[128][72]bf16, A_lo, W_hi[64][72]bf16, W_lo  (pitch 72 = conflict-free ldmatrix)
#define APITCH 72
#define SM_AH  0
#define SM_AL  (SM_AH + MT * APITCH * 2)      // 18432
#define SM_WH  (SM_AL + MT * APITCH * 2)      // 36864
#define SM_WL  (SM_WH + DDIM * APITCH * 2)    // 46080
#define SMEM_BYTES (SM_WL + DDIM * APITCH * 2) // 55296

static __device__ __forceinline__ uint32_t smem_u32(const void* p) {
    uint32_t a;
    asm("{ .reg .u64 t; cvta.to.shared.u64 t, %1; cvt.u32.u64 %0, t; }" : "=r"(a) : "l"(p));
    return a;
}
// pack two floats to bf16x2 (lo = first arg)
static __device__ __forceinline__ uint32_t packbf(float lo_e, float hi_e) {
    uint32_t r;
    asm("cvt.rn.bf16x2.f32 %0, %1, %2;" : "=r"(r) : "f"(hi_e), "f"(lo_e));
    return r;
}
static __device__ __forceinline__ float bf_rt(float x) {
    return __bfloat162float(__float2bfloat16(x));
}

#define LDSM_X4(r, addr)                                                     \
    asm volatile("ldmatrix.sync.aligned.m8n8.x4.shared.b16 {%0,%1,%2,%3}, [%4];" \
        : "=r"((r)[0]), "=r"((r)[1]), "=r"((r)[2]), "=r"((r)[3]) : "r"(addr))
#define LDSM_X4_T(r, addr)                                                   \
    asm volatile("ldmatrix.sync.aligned.m8n8.x4.trans.shared.b16 {%0,%1,%2,%3}, [%4];" \
        : "=r"((r)[0]), "=r"((r)[1]), "=r"((r)[2]), "=r"((r)[3]) : "r"(addr))

#define MMA16816(d, a, b)                                                    \
    asm volatile("mma.sync.aligned.m16n8k16.row.col.f32.bf16.bf16.f32 "      \
        "{%0,%1,%2,%3},{%4,%5,%6,%7},{%8,%9},{%0,%1,%2,%3};"                 \
        : "+f"((d)[0]), "+f"((d)[1]), "+f"((d)[2]), "+f"((d)[3])             \
        : "r"((a)[0]), "r"((a)[1]), "r"((a)[2]), "r"((a)[3]),                \
          "r"((b)[0]), "r"((b)[1]))

__global__ void __launch_bounds__(THREADS, 2)
bilin_hmma(const float* __restrict__ X,   // [B, 32, 64]
           const float* __restrict__ W,   // [496, 64, 64]
           float* __restrict__ out)       // [B, 496, 64]
{
    extern __shared__ char smem[];
    const uint32_t sb  = smem_u32(smem);
    const int tid  = threadIdx.x;
    const int wid  = tid >> 5;
    const int lane = tid & 31;
    const int i    = blockIdx.y;
    const int b0   = blockIdx.x * MT;

    // ---- convert A = X[b0:b0+128, i, :] to bf16 hi/lo smem (once) ----
    {
        const int m = tid;
        const float4* xr = (const float4*)(X + (size_t)(b0 + m) * FD + i * DDIM);
        char* ah = smem + SM_AH + m * (APITCH * 2);
        char* al = smem + SM_AL + m * (APITCH * 2);
        #pragma unroll
        for (int q = 0; q < 16; q++) {
            float4 v = xr[q];
            uint2 h = make_uint2(packbf(v.x, v.y), packbf(v.z, v.w));
            uint2 l = make_uint2(packbf(v.x - bf_rt(v.x), v.y - bf_rt(v.y)),
                                 packbf(v.z - bf_rt(v.z), v.w - bf_rt(v.w)));
            *(uint2*)(ah + q * 8) = h;
            *(uint2*)(al + q * 8) = l;
        }
    }
    __syncthreads();

    // ---- load A fragments once, hold in registers for the whole j loop ----
    // A tile per warp: rows w*32..w*32+31 -> mt in {0,1}, kt in 0..3
    uint32_t ah[2][4][4], al[2][4][4];
    {
        const int r16 = lane & 15;       // row within 16-row tile
        const int h16 = lane >> 4;       // 16B half select
        #pragma unroll
        for (int mt = 0; mt < 2; mt++) {
            const int m = wid * 32 + mt * 16 + r16;
            #pragma unroll
            for (int kt = 0; kt < 4; kt++) {
                uint32_t off = (uint32_t)(m * (APITCH * 2) + kt * 32 + h16 * 16);
                LDSM_X4(ah[mt][kt], sb + SM_AH + off);
                LDSM_X4(al[mt][kt], sb + SM_AL + off);
            }
        }
    }

    const int pbase = i * (63 - i) / 2 - i - 1;   // p = pbase + j

    for (int j = i + 1; j < FFEAT; j++) {
        const int p = pbase + j;

        __syncthreads();   // prior iteration's ldmatrix reads of W done
        // ---- convert W_p -> bf16 hi/lo smem [k][n] (coalesced LDG.128) ----
        {
            const float4* wg = (const float4*)(W + (size_t)p * DDIM * DDIM);
            #pragma unroll
            for (int t = 0; t < 8; t++) {
                const int idx4 = tid + (t << 7);      // 0..1023
                const int k  = idx4 >> 4;
                const int e4 = (idx4 & 15) << 2;
                float4 v = wg[idx4];
                uint2 h = make_uint2(packbf(v.x, v.y), packbf(v.z, v.w));
                uint2 l = make_uint2(packbf(v.x - bf_rt(v.x), v.y - bf_rt(v.y)),
                                     packbf(v.z - bf_rt(v.z), v.w - bf_rt(v.w)));
                const uint32_t off = (uint32_t)(k * (APITCH * 2) + e4 * 2);
                *(uint2*)(smem + SM_WH + off) = h;
                *(uint2*)(smem + SM_WL + off) = l;
            }
        }
        __syncthreads();

        // ---- accumulate D = Xh Wh + Xl Wh + Xh Wl ----
        float acc[2][8][4];
        #pragma unroll
        for (int mt = 0; mt < 2; mt++)
            #pragma unroll
            for (int nt = 0; nt < 8; nt++)
                #pragma unroll
                for (int c = 0; c < 4; c++) acc[mt][nt][c] = 0.f;

        const int kr = lane & 15;       // k row within 16
        const int nh = lane >> 4;       // n-half select
        #pragma unroll
        for (int kt = 0; kt < 4; kt++) {
            #pragma unroll
            for (int nb = 0; nb < 4; nb++) {   // 16 n-cols per load
                uint32_t bh[4], bl[4];
                const uint32_t off = (uint32_t)((kt * 16 + kr) * (APITCH * 2)
                                                + nb * 32 + nh * 16);
                LDSM_X4_T(bh, sb + SM_WH + off);
                LDSM_X4_T(bl, sb + SM_WL + off);
                #pragma unroll
                for (int mt = 0; mt < 2; mt++) {
                    MMA16816(acc[mt][2 * nb + 0], ah[mt][kt], bh + 0);
                    MMA16816(acc[mt][2 * nb + 1], ah[mt][kt], bh + 2);
                    MMA16816(acc[mt][2 * nb + 0], al[mt][kt], bh + 0);
                    MMA16816(acc[mt][2 * nb + 1], al[mt][kt], bh + 2);
                    MMA16816(acc[mt][2 * nb + 0], ah[mt][kt], bl + 0);
                    MMA16816(acc[mt][2 * nb + 1], ah[mt][kt], bl + 2);
                }
            }
        }

        // ---- epilogue: out[m, p, e] = D[m, e] * X[m, j, e] ----
        {
            const int tr = lane >> 2;
            const int tc = (lane & 3) * 2;
            #pragma unroll
            for (int mt = 0; mt < 2; mt++) {
                const int m0 = b0 + wid * 32 + mt * 16 + tr;
                const float* xj0 = X + (size_t)m0 * FD + j * DDIM;
                const float* xj1 = xj0 + 8 * FD;
                float* o0 = out + ((size_t)m0 * P_PAIRS + p) * DDIM;
                float* o1 = o0 + (size_t)8 * P_PAIRS * DDIM;
                #pragma unroll
                for (int nt = 0; nt < 8; nt++) {
                    const int e = nt * 8 + tc;
                    float2 x0 = *(const float2*)(xj0 + e);
                    float2 x1 = *(const float2*)(xj1 + e);
                    float2 r0 = make_float2(acc[mt][nt][0] * x0.x, acc[mt][nt][1] * x0.y);
                    float2 r1 = make_float2(acc[mt][nt][2] * x1.x, acc[mt][nt][3] * x1.y);
                    *(float2*)(o0 + e) = r0;
                    *(float2*)(o1 + e) = r1;
                }
            }
        }
    }
}

extern "C" void kernel_launch(void* const* d_in, const int* in_sizes, int n_in,
                              void* d_out, int out_size) {
    const float* X = (const float*)d_in[0];
    const float* W = (const float*)d_in[1];
    float* out = (float*)d_out;

    const int B = in_sizes[0] / FD;   // 4096

    cudaFuncSetAttribute(bilin_hmma, cudaFuncAttributeMaxDynamicSharedMemorySize, SMEM_BYTES);

    dim3 grid(B / MT, FFEAT - 1);
    bilin_hmma<<<grid, THREADS, SMEM_BYTES>>>(X, W, out);
}